// round 13
// baseline (speedup 1.0000x reference)
#include <cuda_runtime.h>
#include <math.h>

#define MM 63
#define NN 127
#define BB 256
#define OUT_LOSS (4*BB*NN)
#define NI4 16            // capacity: packed col words per check row (pad c=127)
#define NJ4 10            // capacity: packed check words per column (pad m=63)
#define ROTS 9            // padded stride for rot/b1R

__device__ float    g_partials[BB];
__device__ unsigned g_done = 0;

__device__ __forceinline__ int sigma_apply(int c, int sh, int v) {
    int j = c - sh; if (j < 0) j += NN;
    return v ? ((2 * j >= NN) ? 2 * j - NN : 2 * j) : j;
}

__global__ __launch_bounds__(512, 2)
void decode_kernel(const float* __restrict__ soft_in,
                   const int*   __restrict__ labels,
                   const float* __restrict__ H,
                   const float* __restrict__ cw,
                   float*       __restrict__ out) {
    __shared__ float    s_soft[NN + 1];
    __shared__ float    s_rot[128 * ROTS];
    __shared__ float    s_b1R[64 * ROTS];
    __shared__ float    s_corr[NN + 1];
    __shared__ unsigned s_cols4[NI4 * 64];   // [i4*64+m], pre-padded 0x7F
    __shared__ unsigned s_rows4[NJ4 * NN];   // [j4*127+c], pre-padded 0x3F
    __shared__ unsigned s_mask[64][4];       // row bitmasks of H
    __shared__ unsigned s_cmask[128][2];     // column bitmasks (transposed)
    __shared__ int      s_pref[64][4];
    __shared__ int      s_cnt4[64];
    __shared__ float    s_red[16];
    __shared__ float    s_sp;
    __shared__ int      s_maxB;
    __shared__ int      s_last;

    const int tid = threadIdx.x;
    const int b   = blockIdx.x;
    const int wid = tid >> 5, lane = tid & 31;

    // ---- P0: staging, pad fills, row-mask ballots ----
    if (tid < NN) {
        float v = soft_in[b * NN + tid];
        s_soft[tid] = v;
        out[b * NN + tid] = v;               // outs[0]
        s_corr[tid] = 0.f;
    }
    if (tid == NN) s_soft[NN] = 1e38f;
    if (tid >= 128 && tid < 136) s_b1R[63 * ROTS + (tid - 128)] = 0.f;
    if (tid == 137) s_maxB = 0;
    if (tid == 136) {
        float x = cw[0];
        s_sp = (x > 0.f) ? (x + log1pf(expf(-x))) : log1pf(expf(x));
    }
    s_cols4[tid] = 0x7F7F7F7Fu; s_cols4[tid + 512] = 0x7F7F7F7Fu;
    for (int i = tid; i < NJ4 * NN; i += 512) s_rows4[i] = 0x3F3F3F3Fu;
    for (int m = wid; m < MM; m += 16) {
        float v0 = H[m * NN + lane];
        float v1 = H[m * NN + lane + 32];
        float v2 = H[m * NN + lane + 64];
        float v3 = (lane + 96 < NN) ? H[m * NN + lane + 96] : 0.f;
        unsigned b0 = __ballot_sync(~0u, v0 != 0.f);
        unsigned b1 = __ballot_sync(~0u, v1 != 0.f);
        unsigned b2 = __ballot_sync(~0u, v2 != 0.f);
        unsigned b3 = __ballot_sync(~0u, v3 != 0.f);
        if (lane == 0) {
            s_mask[m][0] = b0; s_mask[m][1] = b1;
            s_mask[m][2] = b2; s_mask[m][3] = b3;
        }
    }
    __syncthreads();

    // ---- P1: row prefixes/counts + ballot transpose ----
    if (tid < MM) {
        int m = tid;
        unsigned w0 = s_mask[m][0], w1 = s_mask[m][1];
        unsigned w2 = s_mask[m][2], w3 = s_mask[m][3];
        int p0 = __popc(w0), p1 = __popc(w1), p2 = __popc(w2);
        s_pref[m][0] = 0; s_pref[m][1] = p0;
        s_pref[m][2] = p0 + p1; s_pref[m][3] = p0 + p1 + p2;
        s_cnt4[m] = (p0 + p1 + p2 + __popc(w3) + 3) >> 2;
    }
    for (int op = wid; op < 254; op += 16) {
        int c = op >> 1, q = op & 1;
        int m_l = q * 32 + lane;
        unsigned v = (m_l < MM) ? ((s_mask[m_l][c >> 5] >> (c & 31)) & 1u) : 0u;
        unsigned bal = __ballot_sync(~0u, v);
        if (lane == 0) s_cmask[c][q] = bal;
    }
    __syncthreads();

    // ---- P2: rank-based extraction + rot init ----
    {   // row lists: 8 threads per row, 16 bits each
        int m = tid >> 3, nb = tid & 7;
        if (m < MM) {
            int q = nb >> 1, base = (nb & 1) * 16;
            unsigned msk = s_mask[m][q];
            int pc = s_pref[m][q] + __popc(msk & ((1u << base) - 1u));
            unsigned char* dst = (unsigned char*)s_cols4;
            #pragma unroll
            for (int k = 0; k < 16; ++k) {
                if ((msk >> (base + k)) & 1u) {
                    int r = pc++;
                    dst[((r >> 2) * 64 + m) * 4 + (r & 3)] = (unsigned char)(q * 32 + base + k);
                }
            }
        }
    }
    {   // column lists: 4 threads per column, 16 bits each
        int c = tid >> 2, mb = tid & 3;
        if (c < NN) {
            int q = mb >> 1, base = (mb & 1) * 16;
            unsigned msk = s_cmask[c][q];
            int pc = (q ? __popc(s_cmask[c][0]) : 0) + __popc(msk & ((1u << base) - 1u));
            unsigned char* dst = (unsigned char*)s_rows4;
            #pragma unroll
            for (int k = 0; k < 16; ++k) {
                if ((msk >> (base + k)) & 1u) {
                    int r = pc++;
                    dst[((r >> 2) * NN + c) * 4 + (r & 3)] = (unsigned char)(q * 32 + base + k);
                }
            }
            if (mb == 0) {
                int rc = __popc(s_cmask[c][0]) + __popc(s_cmask[c][1]);
                atomicMax(&s_maxB, (rc + 3) >> 2);
            }
        }
    }
    {   // rot init: rot[c*ROTS+t] = soft[sigma_t(c)]
        int j = tid, c = j >> 3, t = j & 7;
        s_rot[c * ROTS + t] =
            (c < NN) ? s_soft[sigma_apply(c, (t & 3) * 31, t >> 2)] : 1e38f;
        j = tid + 512; c = j >> 3; t = j & 7;
        s_rot[c * ROTS + t] =
            (c < NN) ? s_soft[sigma_apply(c, (t & 3) * 31, t >> 2)] : 1e38f;
    }
    const int  m_a    = tid >> 3;
    const int  t_a    = tid & 7;
    const bool validA = (m_a < MM);
    __syncthreads();

    const float coefA = s_sp * ((t_a >> 2) ? 2.0f : 1.0f);
    const int   cntA  = validA ? s_cnt4[m_a] : 0;
    const int   maxB  = s_maxB;

    // Phase B identity
    const int t_b = tid & 7;
    const int n0  = tid >> 3;
    int cB[2]; bool vB[2];
    #pragma unroll
    for (int r = 0; r < 2; ++r) {
        int n = n0 + 64 * r;
        vB[r] = (n < NN);
        int cb = (t_b >> 2) ? ((n * 64) % NN) : n;
        int c  = cb + (t_b & 3) * 31; if (c >= NN) c -= NN;
        cB[r]  = vB[r] ? c : 0;
    }

    for (int it = 0; it < 3; ++it) {
        // ---------- Phase A: top-2 + argmin + parity ----------
        if (validA) {
            const unsigned* rt = (const unsigned*)&s_rot[t_a];
            unsigned k1a = ~0u, k2a = ~0u, k1b = ~0u, k2b = ~0u, sx = 0u;
            #pragma unroll 4
            for (int i4 = 0; i4 < cntA; ++i4) {
                unsigned w = s_cols4[i4 * 64 + m_a];
                int c0 = w & 255, c1 = (w >> 8) & 255, c2 = (w >> 16) & 255, c3 = w >> 24;
                unsigned u0 = rt[c0 * ROTS], u1 = rt[c1 * ROTS];
                unsigned u2 = rt[c2 * ROTS], u3 = rt[c3 * ROTS];
                sx ^= u0 ^ u1 ^ u2 ^ u3;
                unsigned key0 = (u0 & 0x7FFFFF80u) | (unsigned)c0;
                unsigned key1 = (u1 & 0x7FFFFF80u) | (unsigned)c1;
                unsigned key2 = (u2 & 0x7FFFFF80u) | (unsigned)c2;
                unsigned key3 = (u3 & 0x7FFFFF80u) | (unsigned)c3;
                k2a = min(k2a, max(key0, k1a)); k1a = min(k1a, key0);
                k2b = min(k2b, max(key1, k1b)); k1b = min(k1b, key1);
                k2a = min(k2a, max(key2, k1a)); k1a = min(k1a, key2);
                k2b = min(k2b, max(key3, k1b)); k1b = min(k1b, key3);
            }
            unsigned k1 = min(k1a, k1b);
            unsigned k2 = min(min(k2a, k2b), max(k1a, k1b));
            unsigned a1 = k1 & 0x7FFFFF80u;
            float min1 = __uint_as_float(a1);
            float min2 = __uint_as_float(k2 & 0x7FFFFF80u);
            int   cmin = (int)(k1 & 127u);
            float sg   = a1 ? ((sx & 0x80000000u) ? -1.f : 1.f) : 0.f;
            float cs   = coefA * sg;
            s_b1R[m_a * ROTS + t_a] = cs * min1;
            float ym = s_rot[cmin * ROTS + t_a];
            float s1 = (ym > 0.f) ? 1.f : ((ym < 0.f) ? -1.f : 0.f);
            int  nstar = sigma_apply(cmin, (t_a & 3) * 31, t_a >> 2);
            atomicAdd(&s_corr[nstar], s1 * cs * (min2 - min1));
        }
        __syncthreads();

        // ---------- Phase B: gather + fused update + rot refresh ----------
        float acc[2], yv[2];
        const float* bt = &s_b1R[t_b];
        #pragma unroll
        for (int r = 0; r < 2; ++r) {
            float a = 0.f; yv[r] = 0.f;
            {
                int c = cB[r];
                float sum = 0.f;
                #pragma unroll 2
                for (int j4 = 0; j4 < maxB; ++j4) {
                    unsigned w = s_rows4[j4 * NN + c];
                    sum += bt[(w & 255) * ROTS] + bt[((w >> 8) & 255) * ROTS]
                         + bt[((w >> 16) & 255) * ROTS] + bt[(w >> 24) * ROTS];
                }
                float y = s_soft[vB[r] ? (n0 + 64 * r) : 0];
                yv[r] = y;
                float s1 = (y > 0.f) ? 1.f : ((y < 0.f) ? -1.f : 0.f);
                a = s1 * sum;
                if (t_b == 0 && vB[r]) a += s_corr[n0 + 64 * r];
            }
            acc[r] = a;
        }
        #pragma unroll
        for (int r = 0; r < 2; ++r) {
            acc[r] += __shfl_xor_sync(0xffffffffu, acc[r], 1);
            acc[r] += __shfl_xor_sync(0xffffffffu, acc[r], 2);
            acc[r] += __shfl_xor_sync(0xffffffffu, acc[r], 4);
        }
        #pragma unroll
        for (int r = 0; r < 2; ++r) {
            if (vB[r]) {
                int n = n0 + 64 * r;
                float ns = yv[r] + acc[r] * (1.0f / 12.0f);
                s_rot[cB[r] * ROTS + t_b] = ns;
                if (t_b == 0) {
                    s_corr[n] = 0.f;
                    s_soft[n] = ns;
                    out[(it + 1) * BB * NN + b * NN + n] = ns;
                }
            }
        }
        __syncthreads();
    }

    // ---------- loss: block partial + last-CTA finalize ----------
    float part = 0.f;
    if (tid < NN) {
        float x   = s_soft[tid];
        float lf  = (float)labels[b * NN + tid];
        float sgn = (x > 0.f) ? 1.f : ((x < 0.f) ? -1.f : 0.f);
        float w   = (sgn != 1.f - 2.f * lf) ? 2.0f : 1.0f;
        float z   = -x;
        part = w * (fmaxf(z, 0.f) - z * lf + log1pf(expf(-fabsf(z))));
    }
    #pragma unroll
    for (int off = 16; off; off >>= 1)
        part += __shfl_down_sync(0xffffffffu, part, off);
    if (lane == 0) s_red[wid] = part;
    __syncthreads();
    if (tid < 32) {
        float v = (tid < 16) ? s_red[tid] : 0.f;
        #pragma unroll
        for (int off = 8; off; off >>= 1)
            v += __shfl_down_sync(0xffffffffu, v, off);
        if (tid == 0) {
            g_partials[b] = v;
            __threadfence();
            unsigned old = atomicAdd(&g_done, 1u);
            s_last = (old == (unsigned)(gridDim.x - 1));
        }
    }
    __syncthreads();
    if (s_last) {
        __threadfence();
        float v = (tid < BB) ? g_partials[tid] : 0.f;
        #pragma unroll
        for (int off = 16; off; off >>= 1)
            v += __shfl_down_sync(0xffffffffu, v, off);
        if (lane == 0 && tid < BB) s_red[wid] = v;
        __syncthreads();
        if (tid == 0) {
            float tot = 0.f;
            #pragma unroll
            for (int k = 0; k < 8; ++k) tot += s_red[k];
            out[OUT_LOSS] = tot;
            g_done = 0;                      // self-restore for next replay
        }
    }
}

extern "C" void kernel_launch(void* const* d_in, const int* in_sizes, int n_in,
                              void* d_out, int out_size) {
    const float* soft = (const float*)d_in[0];
    const int*   lab  = (const int*)d_in[1];
    const float* H    = (const float*)d_in[2];
    const float* cw   = (const float*)d_in[3];
    float* out = (float*)d_out;

    decode_kernel<<<BB, 512>>>(soft, lab, H, cw, out);
}

// round 14
// speedup vs baseline: 1.0040x; 1.0040x over previous
#include <cuda_runtime.h>
#include <math.h>

#define MM 63
#define NN 127
#define BB 256
#define OUT_LOSS (4*BB*NN)
#define NI4 16            // capacity: packed col words per check row (pad c=127)
#define NJ4 10            // capacity: packed check words per column (pad m=63)
#define ROTS 9            // padded stride for rot/b1R

__device__ float    g_partials[BB];
__device__ unsigned g_done = 0;

__device__ __forceinline__ int sigma_apply(int c, int sh, int v) {
    int j = c - sh; if (j < 0) j += NN;
    return v ? ((2 * j >= NN) ? 2 * j - NN : 2 * j) : j;
}

__global__ __launch_bounds__(512, 2)
void decode_kernel(const float* __restrict__ soft_in,
                   const int*   __restrict__ labels,
                   const float* __restrict__ H,
                   const float* __restrict__ cw,
                   float*       __restrict__ out) {
    __shared__ float    s_soft[NN + 1];
    __shared__ float    s_rot[128 * ROTS];
    __shared__ float    s_b1R[64 * ROTS];
    __shared__ float    s_corr[NN + 1];
    __shared__ unsigned s_cols4[NI4 * 64];   // [i4*64+m], pre-padded 0x7F
    __shared__ unsigned s_rows4[NJ4 * NN];   // [j4*127+c], pre-padded 0x3F
    __shared__ unsigned s_mask[64][4];       // row bitmasks of H
    __shared__ unsigned s_cmask[128][2];     // column bitmasks (transposed)
    __shared__ int      s_pref[64][4];
    __shared__ int      s_cnt4[64];
    __shared__ float    s_red[16];
    __shared__ float    s_sp;
    __shared__ int      s_maxB;
    __shared__ int      s_last;

    const int tid = threadIdx.x;
    const int b   = blockIdx.x;
    const int wid = tid >> 5, lane = tid & 31;

    // ---- P0: staging, pad fills, row-mask ballots ----
    if (tid < NN) {
        float v = soft_in[b * NN + tid];
        s_soft[tid] = v;
        out[b * NN + tid] = v;               // outs[0]
        s_corr[tid] = 0.f;
    }
    if (tid == NN) s_soft[NN] = 1e38f;
    if (tid >= 128 && tid < 136) s_b1R[63 * ROTS + (tid - 128)] = 0.f;
    if (tid == 137) s_maxB = 0;
    if (tid == 136) {
        float x = cw[0];
        s_sp = (x > 0.f) ? (x + log1pf(expf(-x))) : log1pf(expf(x));
    }
    s_cols4[tid] = 0x7F7F7F7Fu; s_cols4[tid + 512] = 0x7F7F7F7Fu;
    for (int i = tid; i < NJ4 * NN; i += 512) s_rows4[i] = 0x3F3F3F3Fu;
    for (int m = wid; m < MM; m += 16) {
        float v0 = H[m * NN + lane];
        float v1 = H[m * NN + lane + 32];
        float v2 = H[m * NN + lane + 64];
        float v3 = (lane + 96 < NN) ? H[m * NN + lane + 96] : 0.f;
        unsigned b0 = __ballot_sync(~0u, v0 != 0.f);
        unsigned b1 = __ballot_sync(~0u, v1 != 0.f);
        unsigned b2 = __ballot_sync(~0u, v2 != 0.f);
        unsigned b3 = __ballot_sync(~0u, v3 != 0.f);
        if (lane == 0) {
            s_mask[m][0] = b0; s_mask[m][1] = b1;
            s_mask[m][2] = b2; s_mask[m][3] = b3;
        }
    }
    __syncthreads();

    // ---- P1: row prefixes/counts + ballot transpose ----
    if (tid < MM) {
        int m = tid;
        unsigned w0 = s_mask[m][0], w1 = s_mask[m][1];
        unsigned w2 = s_mask[m][2], w3 = s_mask[m][3];
        int p0 = __popc(w0), p1 = __popc(w1), p2 = __popc(w2);
        s_pref[m][0] = 0; s_pref[m][1] = p0;
        s_pref[m][2] = p0 + p1; s_pref[m][3] = p0 + p1 + p2;
        s_cnt4[m] = (p0 + p1 + p2 + __popc(w3) + 3) >> 2;
    }
    for (int op = wid; op < 254; op += 16) {
        int c = op >> 1, q = op & 1;
        int m_l = q * 32 + lane;
        unsigned v = (m_l < MM) ? ((s_mask[m_l][c >> 5] >> (c & 31)) & 1u) : 0u;
        unsigned bal = __ballot_sync(~0u, v);
        if (lane == 0) s_cmask[c][q] = bal;
    }
    __syncthreads();

    // ---- P2: rank-based extraction + rot init ----
    {   // row lists: 8 threads per row, 16 bits each
        int m = tid >> 3, nb = tid & 7;
        if (m < MM) {
            int q = nb >> 1, base = (nb & 1) * 16;
            unsigned msk = s_mask[m][q];
            int pc = s_pref[m][q] + __popc(msk & ((1u << base) - 1u));
            unsigned char* dst = (unsigned char*)s_cols4;
            #pragma unroll
            for (int k = 0; k < 16; ++k) {
                if ((msk >> (base + k)) & 1u) {
                    int r = pc++;
                    dst[((r >> 2) * 64 + m) * 4 + (r & 3)] = (unsigned char)(q * 32 + base + k);
                }
            }
        }
    }
    {   // column lists: 4 threads per column, 16 bits each
        int c = tid >> 2, mb = tid & 3;
        if (c < NN) {
            int q = mb >> 1, base = (mb & 1) * 16;
            unsigned msk = s_cmask[c][q];
            int pc = (q ? __popc(s_cmask[c][0]) : 0) + __popc(msk & ((1u << base) - 1u));
            unsigned char* dst = (unsigned char*)s_rows4;
            #pragma unroll
            for (int k = 0; k < 16; ++k) {
                if ((msk >> (base + k)) & 1u) {
                    int r = pc++;
                    dst[((r >> 2) * NN + c) * 4 + (r & 3)] = (unsigned char)(q * 32 + base + k);
                }
            }
            if (mb == 0) {
                int rc = __popc(s_cmask[c][0]) + __popc(s_cmask[c][1]);
                atomicMax(&s_maxB, (rc + 3) >> 2);
            }
        }
    }
    {   // rot init: rot[c*ROTS+t] = soft[sigma_t(c)]
        int j = tid, c = j >> 3, t = j & 7;
        s_rot[c * ROTS + t] =
            (c < NN) ? s_soft[sigma_apply(c, (t & 3) * 31, t >> 2)] : 1e38f;
        j = tid + 512; c = j >> 3; t = j & 7;
        s_rot[c * ROTS + t] =
            (c < NN) ? s_soft[sigma_apply(c, (t & 3) * 31, t >> 2)] : 1e38f;
    }
    const int  m_a    = tid >> 3;
    const int  t_a    = tid & 7;
    const bool validA = (m_a < MM);
    __syncthreads();

    const float coefA = s_sp * ((t_a >> 2) ? 2.0f : 1.0f);
    const int   cntA  = validA ? s_cnt4[m_a] : 0;
    const int   maxB  = s_maxB;

    // Phase B identity
    const int t_b = tid & 7;
    const int n0  = tid >> 3;
    int cB[2]; bool vB[2];
    #pragma unroll
    for (int r = 0; r < 2; ++r) {
        int n = n0 + 64 * r;
        vB[r] = (n < NN);
        int cb = (t_b >> 2) ? ((n * 64) % NN) : n;
        int c  = cb + (t_b & 3) * 31; if (c >= NN) c -= NN;
        cB[r]  = vB[r] ? c : 0;
    }

    for (int it = 0; it < 3; ++it) {
        // ---------- Phase A: 4-chain top-2 + argmin + parity ----------
        if (validA) {
            const unsigned* rt = (const unsigned*)&s_rot[t_a];
            unsigned k1a = ~0u, k1b = ~0u, k1c = ~0u, k1d = ~0u;
            unsigned k2a = ~0u, k2b = ~0u, k2c = ~0u, k2d = ~0u, sx = 0u;
            #pragma unroll 4
            for (int i4 = 0; i4 < cntA; ++i4) {
                unsigned w = s_cols4[i4 * 64 + m_a];
                int c0 = w & 255, c1 = (w >> 8) & 255, c2 = (w >> 16) & 255, c3 = w >> 24;
                unsigned u0 = rt[c0 * ROTS], u1 = rt[c1 * ROTS];
                unsigned u2 = rt[c2 * ROTS], u3 = rt[c3 * ROTS];
                sx ^= u0 ^ u1 ^ u2 ^ u3;
                unsigned key0 = (u0 & 0x7FFFFF80u) | (unsigned)c0;
                unsigned key1 = (u1 & 0x7FFFFF80u) | (unsigned)c1;
                unsigned key2 = (u2 & 0x7FFFFF80u) | (unsigned)c2;
                unsigned key3 = (u3 & 0x7FFFFF80u) | (unsigned)c3;
                k2a = min(k2a, max(key0, k1a)); k1a = min(k1a, key0);
                k2b = min(k2b, max(key1, k1b)); k1b = min(k1b, key1);
                k2c = min(k2c, max(key2, k1c)); k1c = min(k1c, key2);
                k2d = min(k2d, max(key3, k1d)); k1d = min(k1d, key3);
            }
            // merge 4 chains: k1 = min; second-min of the four k1s via sort identity
            unsigned lo1 = min(k1a, k1b), hi1 = max(k1a, k1b);
            unsigned lo2 = min(k1c, k1d), hi2 = max(k1c, k1d);
            unsigned k1  = min(lo1, lo2);
            unsigned sec = min(max(lo1, lo2), min(hi1, hi2));
            unsigned k2  = min(min(min(k2a, k2b), min(k2c, k2d)), sec);
            unsigned a1 = k1 & 0x7FFFFF80u;
            float min1 = __uint_as_float(a1);
            float min2 = __uint_as_float(k2 & 0x7FFFFF80u);
            int   cmin = (int)(k1 & 127u);
            float sg   = a1 ? ((sx & 0x80000000u) ? -1.f : 1.f) : 0.f;
            float cs   = coefA * sg;
            s_b1R[m_a * ROTS + t_a] = cs * min1;
            float ym = s_rot[cmin * ROTS + t_a];
            float s1 = (ym > 0.f) ? 1.f : ((ym < 0.f) ? -1.f : 0.f);
            int  nstar = sigma_apply(cmin, (t_a & 3) * 31, t_a >> 2);
            atomicAdd(&s_corr[nstar], s1 * cs * (min2 - min1));
        }
        __syncthreads();

        // ---------- Phase B: dual-accumulator gather + fused update ----------
        float acc[2], yv[2];
        const float* bt = &s_b1R[t_b];
        #pragma unroll
        for (int r = 0; r < 2; ++r) {
            float a = 0.f; yv[r] = 0.f;
            {
                int c = cB[r];
                float sum0 = 0.f, sum1 = 0.f;
                #pragma unroll 2
                for (int j4 = 0; j4 < maxB; ++j4) {
                    unsigned w = s_rows4[j4 * NN + c];
                    sum0 += bt[(w & 255) * ROTS] + bt[((w >> 16) & 255) * ROTS];
                    sum1 += bt[((w >> 8) & 255) * ROTS] + bt[(w >> 24) * ROTS];
                }
                float y = s_soft[vB[r] ? (n0 + 64 * r) : 0];
                yv[r] = y;
                float s1 = (y > 0.f) ? 1.f : ((y < 0.f) ? -1.f : 0.f);
                a = s1 * (sum0 + sum1);
                if (t_b == 0 && vB[r]) a += s_corr[n0 + 64 * r];
            }
            acc[r] = a;
        }
        #pragma unroll
        for (int r = 0; r < 2; ++r) {
            acc[r] += __shfl_xor_sync(0xffffffffu, acc[r], 1);
            acc[r] += __shfl_xor_sync(0xffffffffu, acc[r], 2);
            acc[r] += __shfl_xor_sync(0xffffffffu, acc[r], 4);
        }
        #pragma unroll
        for (int r = 0; r < 2; ++r) {
            if (vB[r]) {
                int n = n0 + 64 * r;
                float ns = yv[r] + acc[r] * (1.0f / 12.0f);
                s_rot[cB[r] * ROTS + t_b] = ns;
                if (t_b == 0) {
                    s_corr[n] = 0.f;
                    s_soft[n] = ns;
                    out[(it + 1) * BB * NN + b * NN + n] = ns;
                }
            }
        }
        __syncthreads();
    }

    // ---------- loss: block partial + last-CTA finalize ----------
    float part = 0.f;
    if (tid < NN) {
        float x   = s_soft[tid];
        float lf  = (float)labels[b * NN + tid];
        float sgn = (x > 0.f) ? 1.f : ((x < 0.f) ? -1.f : 0.f);
        float w   = (sgn != 1.f - 2.f * lf) ? 2.0f : 1.0f;
        float z   = -x;
        part = w * (fmaxf(z, 0.f) - z * lf + log1pf(expf(-fabsf(z))));
    }
    #pragma unroll
    for (int off = 16; off; off >>= 1)
        part += __shfl_down_sync(0xffffffffu, part, off);
    if (lane == 0) s_red[wid] = part;
    __syncthreads();
    if (tid < 32) {
        float v = (tid < 16) ? s_red[tid] : 0.f;
        #pragma unroll
        for (int off = 8; off; off >>= 1)
            v += __shfl_down_sync(0xffffffffu, v, off);
        if (tid == 0) {
            g_partials[b] = v;
            __threadfence();
            unsigned old = atomicAdd(&g_done, 1u);
            s_last = (old == (unsigned)(gridDim.x - 1));
        }
    }
    __syncthreads();
    if (s_last) {
        __threadfence();
        float v = (tid < BB) ? g_partials[tid] : 0.f;
        #pragma unroll
        for (int off = 16; off; off >>= 1)
            v += __shfl_down_sync(0xffffffffu, v, off);
        if (lane == 0 && tid < BB) s_red[wid] = v;
        __syncthreads();
        if (tid == 0) {
            float tot = 0.f;
            #pragma unroll
            for (int k = 0; k < 8; ++k) tot += s_red[k];
            out[OUT_LOSS] = tot;
            g_done = 0;                      // self-restore for next replay
        }
    }
}

extern "C" void kernel_launch(void* const* d_in, const int* in_sizes, int n_in,
                              void* d_out, int out_size) {
    const float* soft = (const float*)d_in[0];
    const int*   lab  = (const int*)d_in[1];
    const float* H    = (const float*)d_in[2];
    const float* cw   = (const float*)d_in[3];
    float* out = (float*)d_out;

    decode_kernel<<<BB, 512>>>(soft, lab, H, cw, out);
}

// round 15
// speedup vs baseline: 1.0065x; 1.0024x over previous
#include <cuda_runtime.h>
#include <math.h>

#define MM 63
#define NN 127
#define BB 256
#define OUT_LOSS (4*BB*NN)
#define NI4 16            // capacity: packed col words per check row (pad c=127)
#define NJ4 10            // capacity: packed check words per column (pad m=63)
#define RS  10            // rot stride (even: float2-aligned task pairs)
#define BS  9             // b1R stride (odd: conflict-free scalar gathers)

__device__ float    g_partials[BB];
__device__ unsigned g_done = 0;

__device__ __forceinline__ int sigma_apply(int c, int sh, int v) {
    int j = c - sh; if (j < 0) j += NN;
    return v ? ((2 * j >= NN) ? 2 * j - NN : 2 * j) : j;
}

__global__ __launch_bounds__(512, 2)
void decode_kernel(const float* __restrict__ soft_in,
                   const int*   __restrict__ labels,
                   const float* __restrict__ H,
                   const float* __restrict__ cw,
                   float*       __restrict__ out) {
    __shared__ __align__(16) float s_rot[128 * RS];
    __shared__ float    s_soft[NN + 1];
    __shared__ float    s_b1R[64 * BS];
    __shared__ float    s_corr[NN + 1];
    __shared__ unsigned s_cols4[NI4 * 64];   // [i4*64+m], pre-padded 0x7F
    __shared__ unsigned s_rows4[NJ4 * NN];   // [j4*127+c], pre-padded 0x3F
    __shared__ unsigned s_mask[64][4];       // row bitmasks of H
    __shared__ unsigned s_cmask[128][2];     // column bitmasks (transposed)
    __shared__ int      s_pref[64][4];
    __shared__ int      s_cnt4[64];
    __shared__ float    s_red[16];
    __shared__ float    s_sp;
    __shared__ int      s_maxB;
    __shared__ int      s_last;

    const int tid = threadIdx.x;
    const int b   = blockIdx.x;
    const int wid = tid >> 5, lane = tid & 31;

    // ---- P0: staging, pad fills, row-mask ballots ----
    if (tid < NN) {
        float v = soft_in[b * NN + tid];
        s_soft[tid] = v;
        out[b * NN + tid] = v;               // outs[0]
        s_corr[tid] = 0.f;
    }
    if (tid == NN) s_soft[NN] = 1e38f;
    if (tid >= 128 && tid < 136) s_b1R[63 * BS + (tid - 128)] = 0.f;
    if (tid == 137) s_maxB = 0;
    if (tid == 136) {
        float x = cw[0];
        s_sp = (x > 0.f) ? (x + log1pf(expf(-x))) : log1pf(expf(x));
    }
    s_cols4[tid] = 0x7F7F7F7Fu; s_cols4[tid + 512] = 0x7F7F7F7Fu;
    for (int i = tid; i < NJ4 * NN; i += 512) s_rows4[i] = 0x3F3F3F3Fu;
    for (int m = wid; m < MM; m += 16) {
        float v0 = H[m * NN + lane];
        float v1 = H[m * NN + lane + 32];
        float v2 = H[m * NN + lane + 64];
        float v3 = (lane + 96 < NN) ? H[m * NN + lane + 96] : 0.f;
        unsigned b0 = __ballot_sync(~0u, v0 != 0.f);
        unsigned b1 = __ballot_sync(~0u, v1 != 0.f);
        unsigned b2 = __ballot_sync(~0u, v2 != 0.f);
        unsigned b3 = __ballot_sync(~0u, v3 != 0.f);
        if (lane == 0) {
            s_mask[m][0] = b0; s_mask[m][1] = b1;
            s_mask[m][2] = b2; s_mask[m][3] = b3;
        }
    }
    __syncthreads();

    // ---- P1: row prefixes/counts + ballot transpose ----
    if (tid < MM) {
        int m = tid;
        unsigned w0 = s_mask[m][0], w1 = s_mask[m][1];
        unsigned w2 = s_mask[m][2], w3 = s_mask[m][3];
        int p0 = __popc(w0), p1 = __popc(w1), p2 = __popc(w2);
        s_pref[m][0] = 0; s_pref[m][1] = p0;
        s_pref[m][2] = p0 + p1; s_pref[m][3] = p0 + p1 + p2;
        s_cnt4[m] = (p0 + p1 + p2 + __popc(w3) + 3) >> 2;
    }
    for (int op = wid; op < 254; op += 16) {
        int c = op >> 1, q = op & 1;
        int m_l = q * 32 + lane;
        unsigned v = (m_l < MM) ? ((s_mask[m_l][c >> 5] >> (c & 31)) & 1u) : 0u;
        unsigned bal = __ballot_sync(~0u, v);
        if (lane == 0) s_cmask[c][q] = bal;
    }
    __syncthreads();

    // ---- P2: rank-based extraction + rot init ----
    {   // row lists: 8 threads per row, 16 bits each
        int m = tid >> 3, nb = tid & 7;
        if (m < MM) {
            int q = nb >> 1, base = (nb & 1) * 16;
            unsigned msk = s_mask[m][q];
            int pc = s_pref[m][q] + __popc(msk & ((1u << base) - 1u));
            unsigned char* dst = (unsigned char*)s_cols4;
            #pragma unroll
            for (int k = 0; k < 16; ++k) {
                if ((msk >> (base + k)) & 1u) {
                    int r = pc++;
                    dst[((r >> 2) * 64 + m) * 4 + (r & 3)] = (unsigned char)(q * 32 + base + k);
                }
            }
        }
    }
    {   // column lists: 4 threads per column, 16 bits each
        int c = tid >> 2, mb = tid & 3;
        if (c < NN) {
            int q = mb >> 1, base = (mb & 1) * 16;
            unsigned msk = s_cmask[c][q];
            int pc = (q ? __popc(s_cmask[c][0]) : 0) + __popc(msk & ((1u << base) - 1u));
            unsigned char* dst = (unsigned char*)s_rows4;
            #pragma unroll
            for (int k = 0; k < 16; ++k) {
                if ((msk >> (base + k)) & 1u) {
                    int r = pc++;
                    dst[((r >> 2) * NN + c) * 4 + (r & 3)] = (unsigned char)(q * 32 + base + k);
                }
            }
            if (mb == 0) {
                int rc = __popc(s_cmask[c][0]) + __popc(s_cmask[c][1]);
                atomicMax(&s_maxB, (rc + 3) >> 2);
            }
        }
    }
    // rot init: rot[c*RS+t] = soft[sigma_t(c)], pads = +huge
    for (int j = tid; j < 128 * RS; j += 512) {
        int c = j / RS, t = j - c * RS;
        s_rot[j] = (c < NN && t < 8)
                 ? s_soft[sigma_apply(c, (t & 3) * 31, t >> 2)] : 1e38f;
    }
    // Phase A identity: 4 lanes per check, 2 tasks per lane
    const int  m_a    = tid >> 2;
    const int  tp     = tid & 3;
    const int  t0     = tp * 2, t1 = tp * 2 + 1;
    const bool validA = (m_a < MM);
    __syncthreads();

    const float coef0 = s_sp * ((t0 >> 2) ? 2.0f : 1.0f);
    const float coef1 = s_sp * ((t1 >> 2) ? 2.0f : 1.0f);
    const int   cntA  = validA ? s_cnt4[m_a] : 0;
    const int   maxB  = s_maxB;

    // Phase B identity
    const int t_b = tid & 7;
    const int n0  = tid >> 3;
    int cB[2]; bool vB[2];
    #pragma unroll
    for (int r = 0; r < 2; ++r) {
        int n = n0 + 64 * r;
        vB[r] = (n < NN);
        int cb = (t_b >> 2) ? ((n * 64) % NN) : n;
        int c  = cb + (t_b & 3) * 31; if (c >= NN) c -= NN;
        cB[r]  = vB[r] ? c : 0;
    }

    for (int it = 0; it < 3; ++it) {
        // ---------- Phase A: paired-task top-2 via float2 gathers ----------
        if (validA) {
            const float* rtp = s_rot + t0;
            // task0 chains (x components), task1 chains (y components)
            unsigned k1a = ~0u, k2a = ~0u, k1b = ~0u, k2b = ~0u;
            unsigned l1a = ~0u, l2a = ~0u, l1b = ~0u, l2b = ~0u;
            unsigned sx0 = 0u, sx1 = 0u;
            #pragma unroll 4
            for (int i4 = 0; i4 < cntA; ++i4) {
                unsigned w = s_cols4[i4 * 64 + m_a];
                int c0 = w & 255, c1 = (w >> 8) & 255, c2 = (w >> 16) & 255, c3 = w >> 24;
                float2 f0 = *(const float2*)(rtp + c0 * RS);
                float2 f1 = *(const float2*)(rtp + c1 * RS);
                float2 f2 = *(const float2*)(rtp + c2 * RS);
                float2 f3 = *(const float2*)(rtp + c3 * RS);
                unsigned x0 = __float_as_uint(f0.x), y0 = __float_as_uint(f0.y);
                unsigned x1 = __float_as_uint(f1.x), y1 = __float_as_uint(f1.y);
                unsigned x2 = __float_as_uint(f2.x), y2 = __float_as_uint(f2.y);
                unsigned x3 = __float_as_uint(f3.x), y3 = __float_as_uint(f3.y);
                sx0 ^= x0 ^ x1 ^ x2 ^ x3;
                sx1 ^= y0 ^ y1 ^ y2 ^ y3;
                unsigned kx0 = (x0 & 0x7FFFFF80u) | (unsigned)c0;
                unsigned kx1 = (x1 & 0x7FFFFF80u) | (unsigned)c1;
                unsigned kx2 = (x2 & 0x7FFFFF80u) | (unsigned)c2;
                unsigned kx3 = (x3 & 0x7FFFFF80u) | (unsigned)c3;
                unsigned ky0 = (y0 & 0x7FFFFF80u) | (unsigned)c0;
                unsigned ky1 = (y1 & 0x7FFFFF80u) | (unsigned)c1;
                unsigned ky2 = (y2 & 0x7FFFFF80u) | (unsigned)c2;
                unsigned ky3 = (y3 & 0x7FFFFF80u) | (unsigned)c3;
                k2a = min(k2a, max(kx0, k1a)); k1a = min(k1a, kx0);
                k2b = min(k2b, max(kx1, k1b)); k1b = min(k1b, kx1);
                k2a = min(k2a, max(kx2, k1a)); k1a = min(k1a, kx2);
                k2b = min(k2b, max(kx3, k1b)); k1b = min(k1b, kx3);
                l2a = min(l2a, max(ky0, l1a)); l1a = min(l1a, ky0);
                l2b = min(l2b, max(ky1, l1b)); l1b = min(l1b, ky1);
                l2a = min(l2a, max(ky2, l1a)); l1a = min(l1a, ky2);
                l2b = min(l2b, max(ky3, l1b)); l1b = min(l1b, ky3);
            }
            {   // task t0
                unsigned k1 = min(k1a, k1b);
                unsigned k2 = min(min(k2a, k2b), max(k1a, k1b));
                unsigned a1 = k1 & 0x7FFFFF80u;
                float min1 = __uint_as_float(a1);
                float min2 = __uint_as_float(k2 & 0x7FFFFF80u);
                int   cmin = (int)(k1 & 127u);
                float sg   = a1 ? ((sx0 & 0x80000000u) ? -1.f : 1.f) : 0.f;
                float cs   = coef0 * sg;
                s_b1R[m_a * BS + t0] = cs * min1;
                float ym = s_rot[cmin * RS + t0];
                float s1 = (ym > 0.f) ? 1.f : ((ym < 0.f) ? -1.f : 0.f);
                int  nstar = sigma_apply(cmin, (t0 & 3) * 31, t0 >> 2);
                atomicAdd(&s_corr[nstar], s1 * cs * (min2 - min1));
            }
            {   // task t1
                unsigned k1 = min(l1a, l1b);
                unsigned k2 = min(min(l2a, l2b), max(l1a, l1b));
                unsigned a1 = k1 & 0x7FFFFF80u;
                float min1 = __uint_as_float(a1);
                float min2 = __uint_as_float(k2 & 0x7FFFFF80u);
                int   cmin = (int)(k1 & 127u);
                float sg   = a1 ? ((sx1 & 0x80000000u) ? -1.f : 1.f) : 0.f;
                float cs   = coef1 * sg;
                s_b1R[m_a * BS + t1] = cs * min1;
                float ym = s_rot[cmin * RS + t1];
                float s1 = (ym > 0.f) ? 1.f : ((ym < 0.f) ? -1.f : 0.f);
                int  nstar = sigma_apply(cmin, (t1 & 3) * 31, t1 >> 2);
                atomicAdd(&s_corr[nstar], s1 * cs * (min2 - min1));
            }
        }
        __syncthreads();

        // ---------- Phase B: gather + fused update + rot refresh ----------
        float acc[2], yv[2];
        const float* bt = &s_b1R[t_b];
        #pragma unroll
        for (int r = 0; r < 2; ++r) {
            float a = 0.f; yv[r] = 0.f;
            {
                int c = cB[r];
                float sum0 = 0.f, sum1 = 0.f;
                #pragma unroll 2
                for (int j4 = 0; j4 < maxB; ++j4) {
                    unsigned w = s_rows4[j4 * NN + c];
                    sum0 += bt[(w & 255) * BS] + bt[((w >> 16) & 255) * BS];
                    sum1 += bt[((w >> 8) & 255) * BS] + bt[(w >> 24) * BS];
                }
                float y = s_soft[vB[r] ? (n0 + 64 * r) : 0];
                yv[r] = y;
                float s1 = (y > 0.f) ? 1.f : ((y < 0.f) ? -1.f : 0.f);
                a = s1 * (sum0 + sum1);
                if (t_b == 0 && vB[r]) a += s_corr[n0 + 64 * r];
            }
            acc[r] = a;
        }
        #pragma unroll
        for (int r = 0; r < 2; ++r) {
            acc[r] += __shfl_xor_sync(0xffffffffu, acc[r], 1);
            acc[r] += __shfl_xor_sync(0xffffffffu, acc[r], 2);
            acc[r] += __shfl_xor_sync(0xffffffffu, acc[r], 4);
        }
        #pragma unroll
        for (int r = 0; r < 2; ++r) {
            if (vB[r]) {
                int n = n0 + 64 * r;
                float ns = yv[r] + acc[r] * (1.0f / 12.0f);
                s_rot[cB[r] * RS + t_b] = ns;
                if (t_b == 0) {
                    s_corr[n] = 0.f;
                    s_soft[n] = ns;
                    out[(it + 1) * BB * NN + b * NN + n] = ns;
                }
            }
        }
        __syncthreads();
    }

    // ---------- loss: block partial + last-CTA finalize ----------
    float part = 0.f;
    if (tid < NN) {
        float x   = s_soft[tid];
        float lf  = (float)labels[b * NN + tid];
        float sgn = (x > 0.f) ? 1.f : ((x < 0.f) ? -1.f : 0.f);
        float w   = (sgn != 1.f - 2.f * lf) ? 2.0f : 1.0f;
        float z   = -x;
        part = w * (fmaxf(z, 0.f) - z * lf + log1pf(expf(-fabsf(z))));
    }
    #pragma unroll
    for (int off = 16; off; off >>= 1)
        part += __shfl_down_sync(0xffffffffu, part, off);
    if (lane == 0) s_red[wid] = part;
    __syncthreads();
    if (tid < 32) {
        float v = (tid < 16) ? s_red[tid] : 0.f;
        #pragma unroll
        for (int off = 8; off; off >>= 1)
            v += __shfl_down_sync(0xffffffffu, v, off);
        if (tid == 0) {
            g_partials[b] = v;
            __threadfence();
            unsigned old = atomicAdd(&g_done, 1u);
            s_last = (old == (unsigned)(gridDim.x - 1));
        }
    }
    __syncthreads();
    if (s_last) {
        __threadfence();
        float v = (tid < BB) ? g_partials[tid] : 0.f;
        #pragma unroll
        for (int off = 16; off; off >>= 1)
            v += __shfl_down_sync(0xffffffffu, v, off);
        if (lane == 0 && tid < BB) s_red[wid] = v;
        __syncthreads();
        if (tid == 0) {
            float tot = 0.f;
            #pragma unroll
            for (int k = 0; k < 8; ++k) tot += s_red[k];
            out[OUT_LOSS] = tot;
            g_done = 0;                      // self-restore for next replay
        }
    }
}

extern "C" void kernel_launch(void* const* d_in, const int* in_sizes, int n_in,
                              void* d_out, int out_size) {
    const float* soft = (const float*)d_in[0];
    const int*   lab  = (const int*)d_in[1];
    const float* H    = (const float*)d_in[2];
    const float* cw   = (const float*)d_in[3];
    float* out = (float*)d_out;

    decode_kernel<<<BB, 512>>>(soft, lab, H, cw, out);
}

// round 16
// speedup vs baseline: 1.1242x; 1.1170x over previous
#include <cuda_runtime.h>
#include <math.h>

#define MM 63
#define NN 127
#define BB 256
#define OUT_LOSS (4*BB*NN)
#define NI4 16            // packed col words per check row (pad c=127)
#define NJ4 10            // packed check words per column (pad m=63)
#define RS  10            // rot stride (even: float2 task pairs)
#define BS  12            // b1R stride (float4 task quads)
#define SS  9             // S stride (odd: conflict-free M reads)

__device__ float    g_partials[BB];
__device__ unsigned g_done = 0;

__device__ __forceinline__ int sigma_apply(int c, int sh, int v) {
    int j = c - sh; if (j < 0) j += NN;
    return v ? ((2 * j >= NN) ? 2 * j - NN : 2 * j) : j;
}

__global__ __launch_bounds__(512, 2)
void decode_kernel(const float* __restrict__ soft_in,
                   const int*   __restrict__ labels,
                   const float* __restrict__ H,
                   const float* __restrict__ cw,
                   float*       __restrict__ out) {
    __shared__ __align__(16) float s_rot[128 * RS];
    __shared__ __align__(16) float s_b1R[64 * BS];
    __shared__ float    s_S[NN * SS + 8];
    __shared__ float    s_soft[NN + 1];
    __shared__ float    s_corr[NN + 1];
    __shared__ unsigned s_cols4[NI4 * 64];   // [i4*64+m], pre-padded 0x7F
    __shared__ unsigned s_rows4[NJ4 * NN];   // [j4*127+c], pre-padded 0x3F
    __shared__ unsigned s_mask[64][4];
    __shared__ unsigned s_cmask[128][2];
    __shared__ int      s_pref[64][4];
    __shared__ int      s_cnt4[64];
    __shared__ float    s_red[16];
    __shared__ float    s_sp;
    __shared__ int      s_maxB;
    __shared__ int      s_last;

    const int tid = threadIdx.x;
    const int b   = blockIdx.x;
    const int wid = tid >> 5, lane = tid & 31;

    // ---- P0: staging, pad fills, row-mask ballots ----
    if (tid < NN) {
        float v = soft_in[b * NN + tid];
        s_soft[tid] = v;
        out[b * NN + tid] = v;               // outs[0]
        s_corr[tid] = 0.f;
    }
    if (tid == NN) s_soft[NN] = 1e38f;
    if (tid >= 128 && tid < 136) s_b1R[63 * BS + (tid - 128)] = 0.f;  // pad check
    if (tid == 137) s_maxB = 0;
    if (tid == 136) {
        float x = cw[0];
        s_sp = (x > 0.f) ? (x + log1pf(expf(-x))) : log1pf(expf(x));
    }
    s_cols4[tid] = 0x7F7F7F7Fu; s_cols4[tid + 512] = 0x7F7F7F7Fu;
    for (int i = tid; i < NJ4 * NN; i += 512) s_rows4[i] = 0x3F3F3F3Fu;
    for (int m = wid; m < MM; m += 16) {
        float v0 = H[m * NN + lane];
        float v1 = H[m * NN + lane + 32];
        float v2 = H[m * NN + lane + 64];
        float v3 = (lane + 96 < NN) ? H[m * NN + lane + 96] : 0.f;
        unsigned b0 = __ballot_sync(~0u, v0 != 0.f);
        unsigned b1 = __ballot_sync(~0u, v1 != 0.f);
        unsigned b2 = __ballot_sync(~0u, v2 != 0.f);
        unsigned b3 = __ballot_sync(~0u, v3 != 0.f);
        if (lane == 0) {
            s_mask[m][0] = b0; s_mask[m][1] = b1;
            s_mask[m][2] = b2; s_mask[m][3] = b3;
        }
    }
    __syncthreads();

    // ---- P1: row prefixes/counts + ballot transpose ----
    if (tid < MM) {
        int m = tid;
        unsigned w0 = s_mask[m][0], w1 = s_mask[m][1];
        unsigned w2 = s_mask[m][2], w3 = s_mask[m][3];
        int p0 = __popc(w0), p1 = __popc(w1), p2 = __popc(w2);
        s_pref[m][0] = 0; s_pref[m][1] = p0;
        s_pref[m][2] = p0 + p1; s_pref[m][3] = p0 + p1 + p2;
        s_cnt4[m] = (p0 + p1 + p2 + __popc(w3) + 3) >> 2;
    }
    for (int op = wid; op < 254; op += 16) {
        int c = op >> 1, q = op & 1;
        int m_l = q * 32 + lane;
        unsigned v = (m_l < MM) ? ((s_mask[m_l][c >> 5] >> (c & 31)) & 1u) : 0u;
        unsigned bal = __ballot_sync(~0u, v);
        if (lane == 0) s_cmask[c][q] = bal;
    }
    __syncthreads();

    // ---- P2: rank-based extraction + rot init ----
    {   // row lists: 8 threads per row, 16 bits each
        int m = tid >> 3, nb = tid & 7;
        if (m < MM) {
            int q = nb >> 1, base = (nb & 1) * 16;
            unsigned msk = s_mask[m][q];
            int pc = s_pref[m][q] + __popc(msk & ((1u << base) - 1u));
            unsigned char* dst = (unsigned char*)s_cols4;
            #pragma unroll
            for (int k = 0; k < 16; ++k) {
                if ((msk >> (base + k)) & 1u) {
                    int r = pc++;
                    dst[((r >> 2) * 64 + m) * 4 + (r & 3)] = (unsigned char)(q * 32 + base + k);
                }
            }
        }
    }
    {   // column lists: 4 threads per column, 16 bits each
        int c = tid >> 2, mb = tid & 3;
        if (c < NN) {
            int q = mb >> 1, base = (mb & 1) * 16;
            unsigned msk = s_cmask[c][q];
            int pc = (q ? __popc(s_cmask[c][0]) : 0) + __popc(msk & ((1u << base) - 1u));
            unsigned char* dst = (unsigned char*)s_rows4;
            #pragma unroll
            for (int k = 0; k < 16; ++k) {
                if ((msk >> (base + k)) & 1u) {
                    int r = pc++;
                    dst[((r >> 2) * NN + c) * 4 + (r & 3)] = (unsigned char)(q * 32 + base + k);
                }
            }
            if (mb == 0) {
                int rc = __popc(s_cmask[c][0]) + __popc(s_cmask[c][1]);
                atomicMax(&s_maxB, (rc + 3) >> 2);
            }
        }
    }
    // rot init: rot[c*RS+t] = soft[sigma_t(c)], pads = +huge
    for (int j = tid; j < 128 * RS; j += 512) {
        int c = j / RS, t = j - c * RS;
        s_rot[j] = (c < NN && t < 8)
                 ? s_soft[sigma_apply(c, (t & 3) * 31, t >> 2)] : 1e38f;
    }
    // Phase A identity: 4 lanes per check, 2 tasks per lane
    const int  m_a    = tid >> 2;
    const int  tp     = tid & 3;
    const int  t0     = tp * 2, t1 = tp * 2 + 1;
    const bool validA = (m_a < MM);
    __syncthreads();

    const float coef0 = s_sp * ((t0 >> 2) ? 2.0f : 1.0f);
    const float coef1 = s_sp * ((t1 >> 2) ? 2.0f : 1.0f);
    const int   cntA  = validA ? s_cnt4[m_a] : 0;
    const int   maxB  = s_maxB;

    // Phase S identity: cS = tid>>1 (column), tpS = tid&1 (task quad)
    const int cS  = tid >> 1;
    const int tpS = tid & 1;

    // Phase M identity: t = tid&7, n in {n0, n0+64}
    const int t_b = tid & 7;
    const int n0  = tid >> 3;
    int cB[2]; bool vB[2];
    #pragma unroll
    for (int r = 0; r < 2; ++r) {
        int n = n0 + 64 * r;
        vB[r] = (n < NN);
        int cb = (t_b >> 2) ? ((n * 64) % NN) : n;
        int c  = cb + (t_b & 3) * 31; if (c >= NN) c -= NN;
        cB[r]  = vB[r] ? c : 0;
    }

    for (int it = 0; it < 3; ++it) {
        // ---------- Phase A: paired-task top-2 via float2 gathers ----------
        if (validA) {
            const float* rtp = s_rot + t0;
            unsigned k1a = ~0u, k2a = ~0u, k1b = ~0u, k2b = ~0u;
            unsigned l1a = ~0u, l2a = ~0u, l1b = ~0u, l2b = ~0u;
            unsigned sx0 = 0u, sx1 = 0u;
            #pragma unroll 4
            for (int i4 = 0; i4 < cntA; ++i4) {
                unsigned w = s_cols4[i4 * 64 + m_a];
                int c0 = w & 255, c1 = (w >> 8) & 255, c2 = (w >> 16) & 255, c3 = w >> 24;
                float2 f0 = *(const float2*)(rtp + c0 * RS);
                float2 f1 = *(const float2*)(rtp + c1 * RS);
                float2 f2 = *(const float2*)(rtp + c2 * RS);
                float2 f3 = *(const float2*)(rtp + c3 * RS);
                unsigned x0 = __float_as_uint(f0.x), y0 = __float_as_uint(f0.y);
                unsigned x1 = __float_as_uint(f1.x), y1 = __float_as_uint(f1.y);
                unsigned x2 = __float_as_uint(f2.x), y2 = __float_as_uint(f2.y);
                unsigned x3 = __float_as_uint(f3.x), y3 = __float_as_uint(f3.y);
                sx0 ^= x0 ^ x1 ^ x2 ^ x3;
                sx1 ^= y0 ^ y1 ^ y2 ^ y3;
                unsigned kx0 = (x0 & 0x7FFFFF80u) | (unsigned)c0;
                unsigned kx1 = (x1 & 0x7FFFFF80u) | (unsigned)c1;
                unsigned kx2 = (x2 & 0x7FFFFF80u) | (unsigned)c2;
                unsigned kx3 = (x3 & 0x7FFFFF80u) | (unsigned)c3;
                unsigned ky0 = (y0 & 0x7FFFFF80u) | (unsigned)c0;
                unsigned ky1 = (y1 & 0x7FFFFF80u) | (unsigned)c1;
                unsigned ky2 = (y2 & 0x7FFFFF80u) | (unsigned)c2;
                unsigned ky3 = (y3 & 0x7FFFFF80u) | (unsigned)c3;
                k2a = min(k2a, max(kx0, k1a)); k1a = min(k1a, kx0);
                k2b = min(k2b, max(kx1, k1b)); k1b = min(k1b, kx1);
                k2a = min(k2a, max(kx2, k1a)); k1a = min(k1a, kx2);
                k2b = min(k2b, max(kx3, k1b)); k1b = min(k1b, kx3);
                l2a = min(l2a, max(ky0, l1a)); l1a = min(l1a, ky0);
                l2b = min(l2b, max(ky1, l1b)); l1b = min(l1b, ky1);
                l2a = min(l2a, max(ky2, l1a)); l1a = min(l1a, ky2);
                l2b = min(l2b, max(ky3, l1b)); l1b = min(l1b, ky3);
            }
            float b1v0, b1v1;
            {   // task t0
                unsigned k1 = min(k1a, k1b);
                unsigned k2 = min(min(k2a, k2b), max(k1a, k1b));
                unsigned a1 = k1 & 0x7FFFFF80u;
                float min1 = __uint_as_float(a1);
                float min2 = __uint_as_float(k2 & 0x7FFFFF80u);
                int   cmin = (int)(k1 & 127u);
                float sg   = a1 ? ((sx0 & 0x80000000u) ? -1.f : 1.f) : 0.f;
                float cs   = coef0 * sg;
                b1v0 = cs * min1;
                float ym = s_rot[cmin * RS + t0];
                float s1 = (ym > 0.f) ? 1.f : ((ym < 0.f) ? -1.f : 0.f);
                int  nstar = sigma_apply(cmin, (t0 & 3) * 31, t0 >> 2);
                atomicAdd(&s_corr[nstar], s1 * cs * (min2 - min1));
            }
            {   // task t1
                unsigned k1 = min(l1a, l1b);
                unsigned k2 = min(min(l2a, l2b), max(l1a, l1b));
                unsigned a1 = k1 & 0x7FFFFF80u;
                float min1 = __uint_as_float(a1);
                float min2 = __uint_as_float(k2 & 0x7FFFFF80u);
                int   cmin = (int)(k1 & 127u);
                float sg   = a1 ? ((sx1 & 0x80000000u) ? -1.f : 1.f) : 0.f;
                float cs   = coef1 * sg;
                b1v1 = cs * min1;
                float ym = s_rot[cmin * RS + t1];
                float s1 = (ym > 0.f) ? 1.f : ((ym < 0.f) ? -1.f : 0.f);
                int  nstar = sigma_apply(cmin, (t1 & 3) * 31, t1 >> 2);
                atomicAdd(&s_corr[nstar], s1 * cs * (min2 - min1));
            }
            *(float2*)(s_b1R + m_a * BS + t0) = make_float2(b1v0, b1v1);
        }
        __syncthreads();

        // ---------- Phase S: S[c][t] = sum over rows(c) of b1R[.][t] ----------
        if (cS < NN) {
            const float4* b4 = (const float4*)s_b1R;   // index = m*3 + tpS
            float a0 = 0.f, a1 = 0.f, a2 = 0.f, a3 = 0.f;
            #pragma unroll 2
            for (int j4 = 0; j4 < maxB; ++j4) {
                unsigned w = s_rows4[j4 * NN + cS];
                float4 q0 = b4[(w & 255) * 3 + tpS];
                float4 q1 = b4[((w >> 8) & 255) * 3 + tpS];
                float4 q2 = b4[((w >> 16) & 255) * 3 + tpS];
                float4 q3 = b4[(w >> 24) * 3 + tpS];
                a0 += (q0.x + q1.x) + (q2.x + q3.x);
                a1 += (q0.y + q1.y) + (q2.y + q3.y);
                a2 += (q0.z + q1.z) + (q2.z + q3.z);
                a3 += (q0.w + q1.w) + (q2.w + q3.w);
            }
            float* dst = s_S + cS * SS + tpS * 4;
            dst[0] = a0; dst[1] = a1; dst[2] = a2; dst[3] = a3;
        }
        __syncthreads();

        // ---------- Phase M: acc(n,t) = s1(y)*S[c_t(n)][t] + corr ----------
        float acc[2], yv[2];
        #pragma unroll
        for (int r = 0; r < 2; ++r) {
            float a = 0.f;
            float y = s_soft[vB[r] ? (n0 + 64 * r) : 0];
            yv[r] = y;
            if (vB[r]) {
                float s1 = (y > 0.f) ? 1.f : ((y < 0.f) ? -1.f : 0.f);
                a = s1 * s_S[cB[r] * SS + t_b];
                if (t_b == 0) a += s_corr[n0 + 64 * r];
            }
            acc[r] = a;
        }
        #pragma unroll
        for (int r = 0; r < 2; ++r) {
            acc[r] += __shfl_xor_sync(0xffffffffu, acc[r], 1);
            acc[r] += __shfl_xor_sync(0xffffffffu, acc[r], 2);
            acc[r] += __shfl_xor_sync(0xffffffffu, acc[r], 4);
        }
        #pragma unroll
        for (int r = 0; r < 2; ++r) {
            if (vB[r]) {
                int n = n0 + 64 * r;
                float ns = yv[r] + acc[r] * (1.0f / 12.0f);
                s_rot[cB[r] * RS + t_b] = ns;
                if (t_b == 0) {
                    s_corr[n] = 0.f;
                    s_soft[n] = ns;
                    out[(it + 1) * BB * NN + b * NN + n] = ns;
                }
            }
        }
        __syncthreads();
    }

    // ---------- loss: block partial + last-CTA finalize ----------
    float part = 0.f;
    if (tid < NN) {
        float x   = s_soft[tid];
        float lf  = (float)labels[b * NN + tid];
        float sgn = (x > 0.f) ? 1.f : ((x < 0.f) ? -1.f : 0.f);
        float w   = (sgn != 1.f - 2.f * lf) ? 2.0f : 1.0f;
        float z   = -x;
        part = w * (fmaxf(z, 0.f) - z * lf + log1pf(expf(-fabsf(z))));
    }
    #pragma unroll
    for (int off = 16; off; off >>= 1)
        part += __shfl_down_sync(0xffffffffu, part, off);
    if (lane == 0) s_red[wid] = part;
    __syncthreads();
    if (tid < 32) {
        float v = (tid < 16) ? s_red[tid] : 0.f;
        #pragma unroll
        for (int off = 8; off; off >>= 1)
            v += __shfl_down_sync(0xffffffffu, v, off);
        if (tid == 0) {
            g_partials[b] = v;
            __threadfence();
            unsigned old = atomicAdd(&g_done, 1u);
            s_last = (old == (unsigned)(gridDim.x - 1));
        }
    }
    __syncthreads();
    if (s_last) {
        __threadfence();
        float v = (tid < BB) ? g_partials[tid] : 0.f;
        #pragma unroll
        for (int off = 16; off; off >>= 1)
            v += __shfl_down_sync(0xffffffffu, v, off);
        if (lane == 0 && tid < BB) s_red[wid] = v;
        __syncthreads();
        if (tid == 0) {
            float tot = 0.f;
            #pragma unroll
            for (int k = 0; k < 8; ++k) tot += s_red[k];
            out[OUT_LOSS] = tot;
            g_done = 0;                      // self-restore for next replay
        }
    }
}

extern "C" void kernel_launch(void* const* d_in, const int* in_sizes, int n_in,
                              void* d_out, int out_size) {
    const float* soft = (const float*)d_in[0];
    const int*   lab  = (const int*)d_in[1];
    const float* H    = (const float*)d_in[2];
    const float* cw   = (const float*)d_in[3];
    float* out = (float*)d_out;

    decode_kernel<<<BB, 512>>>(soft, lab, H, cw, out);
}